// round 2
// baseline (speedup 1.0000x reference)
#include <cuda_runtime.h>
#include <cstdint>

// Problem constants (ResetGRU: T=256, B=64, I=512, H=1024, NS=4)
#define TT   256
#define BB   64
#define II   512
#define HH   1024
#define GG   3072
#define NBLK 96      // persistent scan blocks (<=148 SMs -> co-resident)
#define CPB  32      // output columns per scan block (96*32 = 3072)
#define NTHR 256

typedef unsigned long long ull;

// ---------------- device scratch (no allocations allowed) ----------------
__device__ float g_I[(size_t)TT * BB * GG];        // phase-1 post-LN preacts  (~201 MB)
__device__ float g_hhraw[BB * GG];                 // per-step raw hh preacts [b][g]
__device__ ull   g_hTdup[HH * BB];                 // blended h, dup-packed f32x2, [k][b]
__device__ float g_fscratch[(size_t)TT * BB * HH]; // f output scratch if d_out is final-only
__device__ unsigned g_bar;                         // monotonic grid-barrier counter
__device__ int g_idx64;                            // 1 if idx is int64, 0 if int32

// ---------------- f32x2 packed helpers (sm_100a packed-fp32 pipe) ----------------
__device__ __forceinline__ ull pack2(float lo, float hi) {
    ull r; asm("mov.b64 %0, {%1, %2};" : "=l"(r) : "f"(lo), "f"(hi)); return r;
}
__device__ __forceinline__ void unpack2(ull v, float& lo, float& hi) {
    asm("mov.b64 {%0, %1}, %2;" : "=f"(lo), "=f"(hi) : "l"(v));
}
__device__ __forceinline__ void fma2(ull& d, ull a, ull b) {
    asm("fma.rn.f32x2 %0, %1, %2, %0;" : "+l"(d) : "l"(a), "l"(b));
}

// ---------------- L1-bypass load/store (cross-block coherence) ----------------
__device__ __forceinline__ float ldcg32(const float* p) { return __ldcg(p); }
__device__ __forceinline__ ull   ldcg64(const ull* p)   { return __ldcg(p); }
__device__ __forceinline__ void  stcg32(float* p, float v) { __stcg(p, v); }
__device__ __forceinline__ void  stcg64(ull* p, ull v)     { __stcg(p, v); }

// ---------------- block-wide (256-thread) sum of a float pair ----------------
__device__ __forceinline__ float2 block_sum2(float a, float b) {
    __shared__ float2 rb[8];
    const unsigned lane = threadIdx.x & 31u, w = threadIdx.x >> 5;
#pragma unroll
    for (int o = 16; o > 0; o >>= 1) {
        a += __shfl_xor_sync(0xffffffffu, a, o);
        b += __shfl_xor_sync(0xffffffffu, b, o);
    }
    if (lane == 0) rb[w] = make_float2(a, b);
    __syncthreads();
    if (threadIdx.x < 32) {
        float2 v = (lane < 8) ? rb[lane] : make_float2(0.f, 0.f);
#pragma unroll
        for (int o = 4; o > 0; o >>= 1) {
            v.x += __shfl_xor_sync(0xffffffffu, v.x, o);
            v.y += __shfl_xor_sync(0xffffffffu, v.y, o);
        }
        if (lane == 0) rb[0] = v;
    }
    __syncthreads();
    float2 res = rb[0];
    __syncthreads();   // protect rb for the next call
    return res;
}

// ---------------- software grid barrier (persistent kernel) ----------------
__device__ __forceinline__ void grid_sync() {
    __threadfence();          // release this thread's global writes
    __syncthreads();
    if (threadIdx.x == 0) {
        unsigned old = atomicAdd(&g_bar, 1u);
        unsigned target = (old / (unsigned)NBLK + 1u) * (unsigned)NBLK;
        unsigned cur;
        do {
            asm volatile("ld.global.acquire.gpu.u32 %0, [%1];"
                         : "=r"(cur) : "l"(&g_bar) : "memory");
        } while ((int)(cur - target) < 0);   // wrap-safe modular compare
    }
    __syncthreads();
}

// ---------------- idx dtype detection (int64 vs int32) ----------------
__global__ void detect_kernel(const void* idx_raw) {
    if (threadIdx.x == 0 && blockIdx.x == 0) {
        const int* w = (const int*)idx_raw;
        int all_hi_zero = 1;
        for (int i = 0; i < 64; i++) {
            if (w[2 * i + 1] != 0) { all_hi_zero = 0; break; }
        }
        g_idx64 = all_hi_zero;   // 64 odd words all zero => little-endian int64
    }
}

__device__ __forceinline__ long long get_idx(const void* p, int pos, int is64) {
    return is64 ? ((const long long*)p)[pos] : (long long)((const int*)p)[pos];
}

// ============================================================================
// Phase 1 GEMM: C[r][g] = sum_i X[r][i] * Wih[g][i]       (16384 x 3072 x 512)
// 64x64 block tile, k-tile 16, per-thread 4x4 via f32x2 over column pairs.
// ============================================================================
__global__ __launch_bounds__(256)
void p1_gemm(const float* __restrict__ X, const float* __restrict__ W) {
    __shared__ float Xs[16][68];   // [k][row], pad 68 (272B rows, 16B-aligned)
    __shared__ float Ws[16][68];   // [k][col]
    const int tid  = threadIdx.x;
    const int row0 = blockIdx.y * 64;
    const int col0 = blockIdx.x * 64;
    const int rowg = tid >> 4;      // 0..15 -> 4 rows each
    const int colg = tid & 15;      // 0..15 -> 4 cols each
    const int lr   = tid >> 2;      // 0..63 (staging row/col)
    const int lk   = (tid & 3) * 4; // 0,4,8,12

    ull acc[4][2] = {};             // acc[r][colpair], zero bits == (0.f,0.f)

    const float* Xp = X + (size_t)(row0 + lr) * II + lk;
    const float* Wp = W + (size_t)(col0 + lr) * II + lk;

    for (int k0 = 0; k0 < II; k0 += 16) {
        float4 xv = *(const float4*)(Xp + k0);
        float4 wv = *(const float4*)(Wp + k0);
        __syncthreads();
        Xs[lk + 0][lr] = xv.x; Xs[lk + 1][lr] = xv.y;
        Xs[lk + 2][lr] = xv.z; Xs[lk + 3][lr] = xv.w;
        Ws[lk + 0][lr] = wv.x; Ws[lk + 1][lr] = wv.y;
        Ws[lk + 2][lr] = wv.z; Ws[lk + 3][lr] = wv.w;
        __syncthreads();
#pragma unroll
        for (int k = 0; k < 16; k++) {
            float4     aq = *(const float4*)&Xs[k][rowg * 4];
            ulonglong2 wq = *(const ulonglong2*)&Ws[k][colg * 4];
            ull a0 = pack2(aq.x, aq.x), a1 = pack2(aq.y, aq.y);
            ull a2 = pack2(aq.z, aq.z), a3 = pack2(aq.w, aq.w);
            fma2(acc[0][0], wq.x, a0); fma2(acc[0][1], wq.y, a0);
            fma2(acc[1][0], wq.x, a1); fma2(acc[1][1], wq.y, a1);
            fma2(acc[2][0], wq.x, a2); fma2(acc[2][1], wq.y, a2);
            fma2(acc[3][0], wq.x, a3); fma2(acc[3][1], wq.y, a3);
        }
    }
#pragma unroll
    for (int r = 0; r < 4; r++) {
        ulonglong2 o; o.x = acc[r][0]; o.y = acc[r][1];
        *(ulonglong2*)&g_I[(size_t)(row0 + rowg * 4 + r) * GG + col0 + colg * 4] = o;
    }
}

// ============================================================================
// Phase 1 LN: per row (t,b): y = LN_3072(raw + bias)*g_ih + b_ih, then the
// n-chunk (last 1024) re-normalized with ln_in. In place over g_I.
// ============================================================================
__global__ __launch_bounds__(256)
void p1_ln(const float* __restrict__ bias,
           const float* __restrict__ gih, const float* __restrict__ bih,
           const float* __restrict__ gin, const float* __restrict__ bin) {
    float* row = g_I + (size_t)blockIdx.x * GG;
    const int tid = threadIdx.x;
    float v[12]; float s1 = 0.f, s2 = 0.f;
#pragma unroll
    for (int i = 0; i < 12; i++) {
        int g = tid + 256 * i;
        float val = row[g] + bias[g];
        v[i] = val; s1 += val; s2 += val * val;
    }
    float2 s = block_sum2(s1, s2);
    float m    = s.x * (1.f / GG);
    float rstd = rsqrtf(fmaxf(s.y * (1.f / GG) - m * m, 0.f) + 1e-5f);
    float y[12]; float sn1 = 0.f, sn2 = 0.f;
#pragma unroll
    for (int i = 0; i < 12; i++) {
        int g = tid + 256 * i;
        float yy = (v[i] - m) * rstd * gih[g] + bih[g];
        y[i] = yy;
        if (i >= 8) { sn1 += yy; sn2 += yy * yy; }   // n-chunk: g in [2048,3072)
    }
    float2 sn = block_sum2(sn1, sn2);
    float mn    = sn.x * (1.f / HH);
    float rstdn = rsqrtf(fmaxf(sn.y * (1.f / HH) - mn * mn, 0.f) + 1e-5f);
#pragma unroll
    for (int i = 0; i < 12; i++) {
        int g = tid + 256 * i;
        if (i < 8) row[g] = y[i];
        else {
            int j = g - 2048;
            row[g] = (y[i] - mn) * rstdn * gin[j] + bin[j];
        }
    }
}

// ============================================================================
// Persistent scan kernel. 96 blocks x 256 threads.
//  - each block holds Whh cols [bk*32, bk*32+32) in SMEM for all 256 steps
//  - GEMM: per thread 4 cols x 2 batches, f32x2 over col pairs against
//    dup-packed h; h staged global->SMEM in 64-k double-buffered chunks
//  - combine (blocks 0..63, one batch each): LN_3072 + nested LN_1024 + gates,
//    writes f[t], pre-blends h with reset[t+1] for the next step
// ============================================================================
__global__ __launch_bounds__(NTHR, 1)
void scan_kernel(const float* __restrict__ state,
                 const float* __restrict__ reset,
                 const void*  __restrict__ idx_raw,
                 const float* __restrict__ init_state,
                 const float* __restrict__ Whh,
                 const float* __restrict__ bias_hh,
                 const float* __restrict__ lnhh_g, const float* __restrict__ lnhh_b,
                 const float* __restrict__ lnhn_g, const float* __restrict__ lnhn_b,
                 float* __restrict__ fout, float* finalout) {
    extern __shared__ char smem_raw[];
    float* Wt  = (float*)smem_raw;                              // [1024*32] = 128KB
    ull*   dbf = (ull*)(smem_raw + (size_t)HH * CPB * 4);       // [2][4096] = 64KB

    const int tid   = threadIdx.x;
    const int bk    = blockIdx.x;
    const int idx64 = g_idx64;

    // ---- load this block's Whh slice once: Wt[k*32 + c] = Whh[bk*32+c][k]
    {
        const float* Wsrc = Whh + (size_t)bk * CPB * HH;
        for (int e = tid; e < CPB * HH; e += NTHR) {
            int c = e >> 10;          // 0..31
            int k = e & 1023;         // coalesced in k
            Wt[k * CPB + c] = Wsrc[c * HH + k];
        }
    }

    // ---- prestep: blend h0 with reset[0] / init_state[idx[0]]
    const int b = bk;
    float hb[4];
    if (bk < BB) {
        float rst = reset[b];
        long long ix = get_idx(idx_raw, b, idx64);
        const float* ini = init_state + (size_t)ix * HH;
#pragma unroll
        for (int ii = 0; ii < 4; ii++) {
            int j = tid + 256 * ii;
            float v = state[b * HH + j] * (1.f - rst) + ini[j] * rst;
            hb[ii] = v;
            stcg64(&g_hTdup[j * BB + b], pack2(v, v));
        }
    }
    grid_sync();

    const int cg = tid & 7;    // 8 col-groups x 4 cols
    const int bg = tid >> 3;   // 32 batch-groups x 2 batches

    for (int t = 0; t < TT; t++) {
        // ================= GEMM: hhraw[b][g] = sum_k h[k][b] * Whh[g][k]
        ull a00 = 0, a01 = 0, a10 = 0, a11 = 0;
        {   // stage chunk 0
#pragma unroll
            for (int i = 0; i < 16; i++)
                dbf[tid + 256 * i] = ldcg64(&g_hTdup[tid + 256 * i]);
        }
        __syncthreads();
        for (int ch = 0; ch < 16; ch++) {
            const ull* cur = dbf + (ch & 1) * 4096;
            if (ch < 15) {
                ull* nxt = dbf + ((ch + 1) & 1) * 4096;
                const ull* src = g_hTdup + (ch + 1) * 4096;
#pragma unroll
                for (int i = 0; i < 16; i++)
                    nxt[tid + 256 * i] = ldcg64(&src[tid + 256 * i]);
            }
            const float* wbase = Wt + ch * 64 * CPB + cg * 4;
            const ull*   hbase = cur + bg * 2;
#pragma unroll 16
            for (int k = 0; k < 64; k++) {
                ulonglong2 wp = *(const ulonglong2*)(wbase + k * CPB);  // cols c..c+3 @k
                ulonglong2 hp = *(const ulonglong2*)(hbase + k * 64);   // dup h, batches 2bg,2bg+1
                fma2(a00, wp.x, hp.x); fma2(a01, wp.y, hp.x);
                fma2(a10, wp.x, hp.y); fma2(a11, wp.y, hp.y);
            }
            __syncthreads();
        }
        {   // write 4 cols x 2 batches
            int b0  = bg * 2;
            int col = bk * CPB + cg * 4;
            ulonglong2 r0; r0.x = a00; r0.y = a01;
            ulonglong2 r1; r1.x = a10; r1.y = a11;
            __stcg((ulonglong2*)&g_hhraw[(size_t)b0 * GG + col], r0);
            __stcg((ulonglong2*)&g_hhraw[(size_t)(b0 + 1) * GG + col], r1);
        }
        grid_sync();

        // ================= combine (one batch per block, blocks 0..63)
        if (bk < BB) {
            const float* hr = g_hhraw + (size_t)b * GG;
            float v[12]; float s1 = 0.f, s2 = 0.f;
#pragma unroll
            for (int i = 0; i < 12; i++) {
                int g = tid + 256 * i;
                float val = ldcg32(&hr[g]) + bias_hh[g];
                v[i] = val; s1 += val; s2 += val * val;
            }
            float2 s = block_sum2(s1, s2);
            float m    = s.x * (1.f / GG);
            float rstd = rsqrtf(fmaxf(s.y * (1.f / GG) - m * m, 0.f) + 1e-5f);
            float y[12]; float sn1 = 0.f, sn2 = 0.f;
#pragma unroll
            for (int i = 0; i < 12; i++) {
                int g = tid + 256 * i;
                float yy = (v[i] - m) * rstd * lnhh_g[g] + lnhh_b[g];
                y[i] = yy;
                if (i >= 8) { sn1 += yy; sn2 += yy * yy; }
            }
            float2 sn = block_sum2(sn1, sn2);
            float mn    = sn.x * (1.f / HH);
            float rstdn = rsqrtf(fmaxf(sn.y * (1.f / HH) - mn * mn, 0.f) + 1e-5f);

            float rnx = 0.f;
            const float* ininx = init_state;
            if (t + 1 < TT) {
                rnx = reset[(t + 1) * BB + b];
                long long ix = get_idx(idx_raw, (t + 1) * BB + b, idx64);
                ininx = init_state + (size_t)ix * HH;
            }
            const float* Irow = g_I + ((size_t)t * BB + b) * GG;
            float* frow = fout + ((size_t)t * BB + b) * HH;
#pragma unroll
            for (int ii = 0; ii < 4; ii++) {
                int j = tid + 256 * ii;
                float hn = (y[8 + ii] - mn) * rstdn * lnhn_g[j] + lnhn_b[j];
                float xr = Irow[j], xz = Irow[HH + j], xn = Irow[2 * HH + j];
                float rg = 1.f / (1.f + __expf(-(xr + y[ii])));
                float zg = 1.f / (1.f + __expf(-(xz + y[4 + ii])));
                float ng = tanhf(xn + rg * hn);
                float hnew = (1.f - zg) * ng + zg * hb[ii];
                frow[j] = hnew;
                if (t == TT - 1) {
                    if (finalout) finalout[b * HH + j] = hnew;
                    hb[ii] = hnew;
                } else {
                    float v2 = hnew * (1.f - rnx) + ininx[j] * rnx;
                    hb[ii] = v2;
                    stcg64(&g_hTdup[j * BB + b], pack2(v2, v2));
                }
            }
        }
        grid_sync();
    }
}

// ============================================================================
// Host launcher
// ============================================================================
extern "C" void kernel_launch(void* const* d_in, const int* in_sizes, int n_in,
                              void* d_out, int out_size) {
    const float* x     = (const float*)d_in[0];
    const float* state = (const float*)d_in[1];
    const float* reset = (const float*)d_in[2];
    const void*  idx   = d_in[3];
    const float* wih   = (const float*)d_in[4];
    const float* whh   = (const float*)d_in[5];
    const float* bih   = (const float*)d_in[6];
    const float* bhh   = (const float*)d_in[7];
    const float* lnihg = (const float*)d_in[8];
    const float* lnihb = (const float*)d_in[9];
    const float* lnhhg = (const float*)d_in[10];
    const float* lnhhb = (const float*)d_in[11];
    const float* lning = (const float*)d_in[12];
    const float* lninb = (const float*)d_in[13];
    const float* lnhng = (const float*)d_in[14];
    const float* lnhnb = (const float*)d_in[15];
    const float* init  = (const float*)d_in[16];

    float* out = (float*)d_out;
    const long long FSZ = (long long)TT * BB * HH;   // 16,777,216
    float* fout;
    float* finalout = nullptr;
    if ((long long)out_size >= FSZ) {
        fout = out;
        if ((long long)out_size >= FSZ + (long long)BB * HH) finalout = out + FSZ;
    } else {
        void* p = nullptr;
        cudaGetSymbolAddress(&p, g_fscratch);
        fout = (float*)p;
        finalout = (out_size >= BB * HH) ? out : nullptr;  // final-only output
    }

    detect_kernel<<<1, 32>>>(idx);

    dim3 g1(GG / 64, (TT * BB) / 64);
    p1_gemm<<<g1, 256>>>(x, wih);
    p1_ln<<<TT * BB, 256>>>(bih, lnihg, lnihb, lning, lninb);

    const int SMEM_SCAN = HH * CPB * 4 + 2 * 4096 * 8;   // 128KB + 64KB = 196608
    cudaFuncSetAttribute(scan_kernel,
                         cudaFuncAttributeMaxDynamicSharedMemorySize, SMEM_SCAN);
    scan_kernel<<<NBLK, NTHR, SMEM_SCAN>>>(state, reset, idx, init, whh, bhh,
                                           lnhhg, lnhhb, lnhng, lnhnb,
                                           fout, finalout);
}

// round 3
// speedup vs baseline: 2.4178x; 2.4178x over previous
#include <cuda_runtime.h>
#include <cstdint>

// Problem constants (ResetGRU: T=256, B=64, I=512, H=1024, NS=4)
#define TT   256
#define BB   64
#define II   512
#define HH   1024
#define GG   3072
#define NBLK 96      // persistent scan blocks (<=148 SMs -> co-resident)
#define CPB  32      // output columns per scan block (96*32 = 3072)
#define NTHR 256

typedef unsigned long long ull;
typedef unsigned int u32;

// ---------------- device scratch (no allocations allowed) ----------------
__device__ float g_I[(size_t)TT * BB * GG];        // phase-1 post-LN preacts (~201 MB)
__device__ float g_hhraw[BB * GG];                 // per-step raw hh preacts [b][g]
__device__ float g_hswz[HH * BB];                  // tf32 h in B-fragment pair layout
__device__ float g_fscratch[(size_t)TT * BB * HH]; // f scratch if d_out is final-only
__device__ unsigned g_bar;                         // monotonic grid-barrier counter
__device__ int g_idx64;                            // 1 if idx is int64, 0 if int32

// ---------------- f32x2 packed helpers (phase-1 GEMM) ----------------
__device__ __forceinline__ ull pack2(float lo, float hi) {
    ull r; asm("mov.b64 %0, {%1, %2};" : "=l"(r) : "f"(lo), "f"(hi)); return r;
}
__device__ __forceinline__ void fma2(ull& d, ull a, ull b) {
    asm("fma.rn.f32x2 %0, %1, %2, %0;" : "+l"(d) : "l"(a), "l"(b));
}

// ---------------- tf32 / mma / cp.async helpers ----------------
__device__ __forceinline__ u32 to_tf32(float f) {
    u32 r; asm("cvt.rna.tf32.f32 %0, %1;" : "=r"(r) : "f"(f)); return r;
}
__device__ __forceinline__ void mma_tf32(float& d0, float& d1, float& d2, float& d3,
                                         u32 a0, u32 a1, u32 a2, u32 a3,
                                         u32 b0, u32 b1) {
    asm volatile("mma.sync.aligned.m16n8k8.row.col.f32.tf32.tf32.f32 "
                 "{%0,%1,%2,%3}, {%4,%5,%6,%7}, {%8,%9}, {%0,%1,%2,%3};"
                 : "+f"(d0), "+f"(d1), "+f"(d2), "+f"(d3)
                 : "r"(a0), "r"(a1), "r"(a2), "r"(a3), "r"(b0), "r"(b1));
}
__device__ __forceinline__ void cpasync16(u32 dst, const void* src) {
    asm volatile("cp.async.cg.shared.global [%0], [%1], 16;" :: "r"(dst), "l"(src));
}
__device__ __forceinline__ void cp_commit() { asm volatile("cp.async.commit_group;"); }
__device__ __forceinline__ void cp_wait1()  { asm volatile("cp.async.wait_group 1;"); }
__device__ __forceinline__ void cp_wait0()  { asm volatile("cp.async.wait_group 0;"); }

// ---------------- L1-bypass load/store (cross-block coherence) ----------------
__device__ __forceinline__ float ldcg32(const float* p) { return __ldcg(p); }
__device__ __forceinline__ void  stcg32(float* p, float v) { __stcg(p, v); }

// ---------------- block-wide (256-thread) sum of a float pair ----------------
__device__ __forceinline__ float2 block_sum2(float a, float b) {
    __shared__ float2 rb[8];
    const unsigned lane = threadIdx.x & 31u, w = threadIdx.x >> 5;
#pragma unroll
    for (int o = 16; o > 0; o >>= 1) {
        a += __shfl_xor_sync(0xffffffffu, a, o);
        b += __shfl_xor_sync(0xffffffffu, b, o);
    }
    if (lane == 0) rb[w] = make_float2(a, b);
    __syncthreads();
    if (threadIdx.x < 32) {
        float2 v = (lane < 8) ? rb[lane] : make_float2(0.f, 0.f);
#pragma unroll
        for (int o = 4; o > 0; o >>= 1) {
            v.x += __shfl_xor_sync(0xffffffffu, v.x, o);
            v.y += __shfl_xor_sync(0xffffffffu, v.y, o);
        }
        if (lane == 0) rb[0] = v;
    }
    __syncthreads();
    float2 res = rb[0];
    __syncthreads();
    return res;
}

// ---------------- software grid barrier (persistent kernel) ----------------
__device__ __forceinline__ void grid_sync() {
    __threadfence();
    __syncthreads();
    if (threadIdx.x == 0) {
        unsigned old = atomicAdd(&g_bar, 1u);
        unsigned target = (old / (unsigned)NBLK + 1u) * (unsigned)NBLK;
        unsigned cur;
        do {
            asm volatile("ld.global.acquire.gpu.u32 %0, [%1];"
                         : "=r"(cur) : "l"(&g_bar) : "memory");
        } while ((int)(cur - target) < 0);
    }
    __syncthreads();
}

// ---------------- idx dtype detection (int64 vs int32) ----------------
__global__ void detect_kernel(const void* idx_raw) {
    if (threadIdx.x == 0 && blockIdx.x == 0) {
        const int* w = (const int*)idx_raw;
        int all_hi_zero = 1;
        for (int i = 0; i < 64; i++) {
            if (w[2 * i + 1] != 0) { all_hi_zero = 0; break; }
        }
        g_idx64 = all_hi_zero;
    }
}
__device__ __forceinline__ long long get_idx(const void* p, int pos, int is64) {
    return is64 ? ((const long long*)p)[pos] : (long long)((const int*)p)[pos];
}

// h -> B-fragment pair-layout index (float units):
// pair p of (k8,b) = (h[k8*8+p], h[k8*8+p+4])
__device__ __forceinline__ int hswz_idx(int j, int b) {
    int k8 = j >> 3, kin = j & 7;
    return ((k8 * 64 + b) * 4 + (kin & 3)) * 2 + (kin >> 2);
}

// ============================================================================
// Phase 1 GEMM (unchanged from R2): C[r][g] = sum_i X[r][i]*Wih[g][i]
// ============================================================================
__global__ __launch_bounds__(256)
void p1_gemm(const float* __restrict__ X, const float* __restrict__ W) {
    __shared__ float Xs[16][68];
    __shared__ float Ws[16][68];
    const int tid  = threadIdx.x;
    const int row0 = blockIdx.y * 64;
    const int col0 = blockIdx.x * 64;
    const int rowg = tid >> 4;
    const int colg = tid & 15;
    const int lr   = tid >> 2;
    const int lk   = (tid & 3) * 4;

    ull acc[4][2] = {};
    const float* Xp = X + (size_t)(row0 + lr) * II + lk;
    const float* Wp = W + (size_t)(col0 + lr) * II + lk;

    for (int k0 = 0; k0 < II; k0 += 16) {
        float4 xv = *(const float4*)(Xp + k0);
        float4 wv = *(const float4*)(Wp + k0);
        __syncthreads();
        Xs[lk + 0][lr] = xv.x; Xs[lk + 1][lr] = xv.y;
        Xs[lk + 2][lr] = xv.z; Xs[lk + 3][lr] = xv.w;
        Ws[lk + 0][lr] = wv.x; Ws[lk + 1][lr] = wv.y;
        Ws[lk + 2][lr] = wv.z; Ws[lk + 3][lr] = wv.w;
        __syncthreads();
#pragma unroll
        for (int k = 0; k < 16; k++) {
            float4     aq = *(const float4*)&Xs[k][rowg * 4];
            ulonglong2 wq = *(const ulonglong2*)&Ws[k][colg * 4];
            ull a0 = pack2(aq.x, aq.x), a1 = pack2(aq.y, aq.y);
            ull a2 = pack2(aq.z, aq.z), a3 = pack2(aq.w, aq.w);
            fma2(acc[0][0], wq.x, a0); fma2(acc[0][1], wq.y, a0);
            fma2(acc[1][0], wq.x, a1); fma2(acc[1][1], wq.y, a1);
            fma2(acc[2][0], wq.x, a2); fma2(acc[2][1], wq.y, a2);
            fma2(acc[3][0], wq.x, a3); fma2(acc[3][1], wq.y, a3);
        }
    }
#pragma unroll
    for (int r = 0; r < 4; r++) {
        ulonglong2 o; o.x = acc[r][0]; o.y = acc[r][1];
        *(ulonglong2*)&g_I[(size_t)(row0 + rowg * 4 + r) * GG + col0 + colg * 4] = o;
    }
}

// ============================================================================
// Phase 1 LN (unchanged from R2)
// ============================================================================
__global__ __launch_bounds__(256)
void p1_ln(const float* __restrict__ bias,
           const float* __restrict__ gih, const float* __restrict__ bih,
           const float* __restrict__ gin, const float* __restrict__ bin) {
    float* row = g_I + (size_t)blockIdx.x * GG;
    const int tid = threadIdx.x;
    float v[12]; float s1 = 0.f, s2 = 0.f;
#pragma unroll
    for (int i = 0; i < 12; i++) {
        int g = tid + 256 * i;
        float val = row[g] + bias[g];
        v[i] = val; s1 += val; s2 += val * val;
    }
    float2 s = block_sum2(s1, s2);
    float m    = s.x * (1.f / GG);
    float rstd = rsqrtf(fmaxf(s.y * (1.f / GG) - m * m, 0.f) + 1e-5f);
    float y[12]; float sn1 = 0.f, sn2 = 0.f;
#pragma unroll
    for (int i = 0; i < 12; i++) {
        int g = tid + 256 * i;
        float yy = (v[i] - m) * rstd * gih[g] + bih[g];
        y[i] = yy;
        if (i >= 8) { sn1 += yy; sn2 += yy * yy; }
    }
    float2 sn = block_sum2(sn1, sn2);
    float mn    = sn.x * (1.f / HH);
    float rstdn = rsqrtf(fmaxf(sn.y * (1.f / HH) - mn * mn, 0.f) + 1e-5f);
#pragma unroll
    for (int i = 0; i < 12; i++) {
        int g = tid + 256 * i;
        if (i < 8) row[g] = y[i];
        else {
            int j = g - 2048;
            row[g] = (y[i] - mn) * rstdn * gin[j] + bin[j];
        }
    }
}

// ============================================================================
// Persistent scan kernel, tf32 tensor-core GEMM.
// SMEM: Wt (A-frag-ordered W_hh slice, 128KB) + hbuf (2x32KB h chunks).
// Warps 0-3: mma compute (warp w: mi=w&1, ng=w>>1; m16 x n32, 16 fp32 accs).
// Warps 4-7: cp.async staging of h chunks (double-buffered).
// ============================================================================
__global__ __launch_bounds__(NTHR, 1)
void scan_kernel(const float* __restrict__ state,
                 const float* __restrict__ reset,
                 const void*  __restrict__ idx_raw,
                 const float* __restrict__ init_state,
                 const float* __restrict__ Whh,
                 const float* __restrict__ bias_hh,
                 const float* __restrict__ lnhh_g, const float* __restrict__ lnhh_b,
                 const float* __restrict__ lnhn_g, const float* __restrict__ lnhn_b,
                 float* __restrict__ fout, float* finalout) {
    extern __shared__ u32 sm[];
    u32* Wt      = sm;                       // 32768 u32 = 128KB
    u32* hbuf    = sm + 32768;               // 16384 u32 = 64KB (2 x 32KB)
    float* scratch = (float*)(sm + 32768);   // epilogue reuse of hbuf[0] (8KB)

    const int tid  = threadIdx.x;
    const int bk   = blockIdx.x;
    const int lane = tid & 31;
    const int wid  = tid >> 5;
    const int idx64 = g_idx64;

    // ---- fill Wt in exact A-fragment order, tf32-rounded (once) ----
    // float index e = ((k8*2+mi)*32 + lane)*4 + jj
    // a0=(c,k) a1=(c+8,k) a2=(c,k+4) a3=(c+8,k+4); c=mi*16+(l>>2), k=k8*8+(l&3)
    for (int e = tid; e < 32768; e += NTHR) {
        int jj = e & 3, l = (e >> 2) & 31, mi_ = (e >> 7) & 1, k8 = e >> 8;
        int c = bk * CPB + mi_ * 16 + (l >> 2) + ((jj & 1) << 3);
        int k = k8 * 8 + (l & 3) + ((jj >> 1) << 2);
        Wt[e] = to_tf32(Whh[(size_t)c * HH + k]);
    }

    // ---- prestep: blend h0 with reset[0]/init_state[idx[0]] ----
    const int b = bk;
    float hb[4];
    if (bk < BB) {
        float rst = reset[b];
        long long ix = get_idx(idx_raw, b, idx64);
        const float* ini = init_state + (size_t)ix * HH;
#pragma unroll
        for (int ii = 0; ii < 4; ii++) {
            int j = tid + 256 * ii;
            float v = state[b * HH + j] * (1.f - rst) + ini[j] * rst;
            hb[ii] = v;
            stcg32(&g_hswz[hswz_idx(j, b)], __uint_as_float(to_tf32(v)));
        }
    }
    grid_sync();

    const bool is_compute = (wid < 4);
    const int mi   = wid & 1;
    const int ng   = (wid >> 1) & 1;
    const int sidx = tid - 128;                              // stager id 0..127
    const u32 hbuf_s = (u32)__cvta_generic_to_shared(hbuf);

    for (int t = 0; t < TT; t++) {
        float acc[4][4];
#pragma unroll
        for (int a = 0; a < 4; a++)
#pragma unroll
            for (int q = 0; q < 4; q++) acc[a][q] = 0.f;

        // stage chunk 0 (32KB = k8 in [0,16))
        if (tid >= 128) {
            const char* src = (const char*)g_hswz;
#pragma unroll
            for (int i = 0; i < 16; i++) {
                int o = (sidx + 128 * i) * 16;
                cpasync16(hbuf_s + o, src + o);
            }
            cp_commit();
        }

        for (int ch = 0; ch < 8; ch++) {
            if (tid >= 128) {
                if (ch < 7) {
                    const char* src = (const char*)g_hswz + (size_t)(ch + 1) * 32768;
                    u32 dst = hbuf_s + ((ch + 1) & 1) * 32768;
#pragma unroll
                    for (int i = 0; i < 16; i++) {
                        int o = (sidx + 128 * i) * 16;
                        cpasync16(dst + o, src + o);
                    }
                    cp_commit();
                    cp_wait1();
                } else {
                    cp_wait0();
                }
            }
            __syncthreads();       // buf[ch&1] ready for all
            if (is_compute) {
                const u32* buf = hbuf + (ch & 1) * 8192;
                int aoff  = (ch * 16) * 256 + (mi * 32 + lane) * 4;
                int bbase = (ng * 32 + (lane >> 2)) * 8 + (lane & 3) * 2;
#pragma unroll
                for (int k8l = 0; k8l < 16; k8l++) {
                    uint4 A = *reinterpret_cast<const uint4*>(&Wt[aoff]);
                    const u32* brow = buf + bbase + k8l * 512;
#pragma unroll
                    for (int tle = 0; tle < 4; tle++) {
                        uint2 Bf = *reinterpret_cast<const uint2*>(&brow[tle * 64]);
                        mma_tf32(acc[tle][0], acc[tle][1], acc[tle][2], acc[tle][3],
                                 A.x, A.y, A.z, A.w, Bf.x, Bf.y);
                    }
                    aoff += 256;
                }
            }
            __syncthreads();       // compute done before buf reuse
        }

        // ---- epilogue: fragments -> scratch[b][g_local], then coalesced stcg ----
        if (is_compute) {
#pragma unroll
            for (int tle = 0; tle < 4; tle++) {
                int nb = (ng * 4 + tle) * 8 + (lane & 3) * 2;
                int gl = mi * 16 + (lane >> 2);
                scratch[nb * 32 + gl]           = acc[tle][0];
                scratch[(nb + 1) * 32 + gl]     = acc[tle][1];
                scratch[nb * 32 + gl + 8]       = acc[tle][2];
                scratch[(nb + 1) * 32 + gl + 8] = acc[tle][3];
            }
        }
        __syncthreads();
        {
            int bb2 = tid >> 2;                 // batch 0..63
            int gl  = (tid & 3) * 8;            // 0,8,16,24
            float4 v0 = *reinterpret_cast<float4*>(&scratch[bb2 * 32 + gl]);
            float4 v1 = *reinterpret_cast<float4*>(&scratch[bb2 * 32 + gl + 4]);
            __stcg((float4*)&g_hhraw[(size_t)bb2 * GG + bk * CPB + gl], v0);
            __stcg((float4*)&g_hhraw[(size_t)bb2 * GG + bk * CPB + gl + 4], v1);
        }
        grid_sync();

        // ---- combine (one batch per block, blocks 0..63) ----
        if (bk < BB) {
            const float* hr = g_hhraw + (size_t)b * GG;
            float v[12]; float s1 = 0.f, s2 = 0.f;
#pragma unroll
            for (int i = 0; i < 12; i++) {
                int g = tid + 256 * i;
                float val = ldcg32(&hr[g]) + bias_hh[g];
                v[i] = val; s1 += val; s2 += val * val;
            }
            float2 s = block_sum2(s1, s2);
            float m    = s.x * (1.f / GG);
            float rstd = rsqrtf(fmaxf(s.y * (1.f / GG) - m * m, 0.f) + 1e-5f);
            float y[12]; float sn1 = 0.f, sn2 = 0.f;
#pragma unroll
            for (int i = 0; i < 12; i++) {
                int g = tid + 256 * i;
                float yy = (v[i] - m) * rstd * lnhh_g[g] + lnhh_b[g];
                y[i] = yy;
                if (i >= 8) { sn1 += yy; sn2 += yy * yy; }
            }
            float2 sn = block_sum2(sn1, sn2);
            float mn    = sn.x * (1.f / HH);
            float rstdn = rsqrtf(fmaxf(sn.y * (1.f / HH) - mn * mn, 0.f) + 1e-5f);

            float rnx = 0.f;
            const float* ininx = init_state;
            if (t + 1 < TT) {
                rnx = reset[(t + 1) * BB + b];
                long long ix = get_idx(idx_raw, (t + 1) * BB + b, idx64);
                ininx = init_state + (size_t)ix * HH;
            }
            const float* Irow = g_I + ((size_t)t * BB + b) * GG;
            float* frow = fout + ((size_t)t * BB + b) * HH;
#pragma unroll
            for (int ii = 0; ii < 4; ii++) {
                int j = tid + 256 * ii;
                float hn = (y[8 + ii] - mn) * rstdn * lnhn_g[j] + lnhn_b[j];
                float xr = Irow[j], xz = Irow[HH + j], xn = Irow[2 * HH + j];
                float rg = 1.f / (1.f + __expf(-(xr + y[ii])));
                float zg = 1.f / (1.f + __expf(-(xz + y[4 + ii])));
                float ngt = tanhf(xn + rg * hn);
                float hnew = (1.f - zg) * ngt + zg * hb[ii];
                frow[j] = hnew;
                if (t == TT - 1) {
                    if (finalout) finalout[b * HH + j] = hnew;
                    hb[ii] = hnew;
                } else {
                    float v2 = hnew * (1.f - rnx) + ininx[j] * rnx;
                    hb[ii] = v2;
                    stcg32(&g_hswz[hswz_idx(j, b)], __uint_as_float(to_tf32(v2)));
                }
            }
        }
        grid_sync();
    }
}

// ============================================================================
// Host launcher
// ============================================================================
extern "C" void kernel_launch(void* const* d_in, const int* in_sizes, int n_in,
                              void* d_out, int out_size) {
    const float* x     = (const float*)d_in[0];
    const float* state = (const float*)d_in[1];
    const float* reset = (const float*)d_in[2];
    const void*  idx   = d_in[3];
    const float* wih   = (const float*)d_in[4];
    const float* whh   = (const float*)d_in[5];
    const float* bih   = (const float*)d_in[6];
    const float* bhh   = (const float*)d_in[7];
    const float* lnihg = (const float*)d_in[8];
    const float* lnihb = (const float*)d_in[9];
    const float* lnhhg = (const float*)d_in[10];
    const float* lnhhb = (const float*)d_in[11];
    const float* lning = (const float*)d_in[12];
    const float* lninb = (const float*)d_in[13];
    const float* lnhng = (const float*)d_in[14];
    const float* lnhnb = (const float*)d_in[15];
    const float* init  = (const float*)d_in[16];

    float* out = (float*)d_out;
    const long long FSZ = (long long)TT * BB * HH;
    float* fout;
    float* finalout = nullptr;
    if ((long long)out_size >= FSZ) {
        fout = out;
        if ((long long)out_size >= FSZ + (long long)BB * HH) finalout = out + FSZ;
    } else {
        void* p = nullptr;
        cudaGetSymbolAddress(&p, g_fscratch);
        fout = (float*)p;
        finalout = (out_size >= BB * HH) ? out : nullptr;
    }

    detect_kernel<<<1, 32>>>(idx);

    dim3 g1(GG / 64, (TT * BB) / 64);
    p1_gemm<<<g1, 256>>>(x, wih);
    p1_ln<<<TT * BB, 256>>>(bih, lnihg, lnihb, lning, lninb);

    const int SMEM_SCAN = (32768 + 16384) * 4;   // 128KB Wt + 64KB hbuf = 192KB
    cudaFuncSetAttribute(scan_kernel,
                         cudaFuncAttributeMaxDynamicSharedMemorySize, SMEM_SCAN);
    scan_kernel<<<NBLK, NTHR, SMEM_SCAN>>>(state, reset, idx, init, whh, bhh,
                                           lnhhg, lnhhb, lnhng, lnhnb,
                                           fout, finalout);
}